// round 9
// baseline (speedup 1.0000x reference)
#include <cuda_runtime.h>
#include <math_constants.h>

#define EPS_WH 1e-07f
#define MAX_WH 10000000.0f
#define THREADS 256
#define CHUNK_BYTES 16384         // 16 KB per TMA bulk copy
#define CHUNK_F4 (CHUNK_BYTES / 16)   // 1024 float4 per chunk
#define F4_PER_THREAD (CHUNK_F4 / THREADS)  // 4

// Scratch: per-block argmax keys + completion counter.
__device__ unsigned long long g_keys[4096];
__device__ int g_count;       // zero-initialized; reset by last block each run

__device__ __forceinline__ float clip_wh(float v) {
    return fminf(fmaxf(v, EPS_WH), MAX_WH);
}

__device__ __forceinline__ unsigned int f2sortable(float f) {
    unsigned int u = __float_as_uint(f);
    return (u & 0x80000000u) ? ~u : (u | 0x80000000u);
}

__device__ __forceinline__ unsigned int smem_u32(const void* p) {
    unsigned int a;
    asm("{ .reg .u64 t; cvta.to.shared.u64 t, %1; cvt.u32.u64 %0, t; }"
        : "=r"(a) : "l"(p));
    return a;
}

__device__ __forceinline__ void mbar_init(unsigned int mbar, unsigned int cnt) {
    asm volatile("mbarrier.init.shared.b64 [%0], %1;" :: "r"(mbar), "r"(cnt) : "memory");
}
__device__ __forceinline__ void mbar_expect_tx(unsigned int mbar, unsigned int bytes) {
    asm volatile("mbarrier.arrive.expect_tx.shared.b64 _, [%0], %1;"
                 :: "r"(mbar), "r"(bytes) : "memory");
}
__device__ __forceinline__ void mbar_wait(unsigned int mbar, unsigned int parity) {
    asm volatile(
        "{\n\t"
        ".reg .pred P;\n\t"
        "WAIT_%=:\n\t"
        "mbarrier.try_wait.parity.acquire.cta.shared::cta.b64 P, [%0], %1, 0x989680;\n\t"
        "@P bra.uni DONE_%=;\n\t"
        "bra.uni WAIT_%=;\n\t"
        "DONE_%=:\n\t"
        "}" :: "r"(mbar), "r"(parity) : "memory");
}
__device__ __forceinline__ void bulk_g2s(unsigned int dst, const void* src,
                                         unsigned int bytes, unsigned int mbar) {
    asm volatile(
        "cp.async.bulk.shared::cta.global.mbarrier::complete_tx::bytes "
        "[%0], [%1], %2, [%3];"
        :: "r"(dst), "l"(src), "r"(bytes), "r"(mbar) : "memory");
}

__device__ __forceinline__ float gwd_loss_one(
    const float* __restrict__ ab, const float* __restrict__ trig,
    const float* __restrict__ center, const float* __restrict__ target,
    int b, int idx, int HW)
{
    const float* abb = ab   + (size_t)b * 2 * HW;
    const float* tgb = trig + (size_t)b * 2 * HW;
    float a1    = __ldg(&abb[idx]);
    float a2    = __ldg(&abb[HW + idx]);
    float sin2A = __ldg(&tgb[idx]);
    float cos2A = __ldg(&tgb[HW + idx]);

    // deg roundtrip in the reference is the identity; stay in radians
    float r_p = 0.5f * atan2f(sin2A, cos2A);
    float xp = center[2 * b], yp = center[2 * b + 1];
    float s1p = 0.5f * clip_wh(2.0f * a1);
    float s2p = 0.5f * clip_wh(2.0f * a2);
    float cp = cosf(r_p), sp = sinf(r_p);

    float xt = target[5 * b + 0];
    float yt = target[5 * b + 1];
    float s1t = 0.5f * clip_wh(target[5 * b + 2]);
    float s2t = 0.5f * clip_wh(target[5 * b + 3]);
    float r_t = target[5 * b + 4] * (CUDART_PI_F / 180.0f);
    float ct = cosf(r_t), st = sinf(r_t);

    float dx = xp - xt, dy = yp - yt;
    float xy_dist = dx * dx + dy * dy;

    float sp1_2 = s1p * s1p, sp2_2 = s2p * s2p;
    float st1_2 = s1t * s1t, st2_2 = s2t * s2t;

    float Ap = sp1_2 * cp * cp + sp2_2 * sp * sp;
    float Bp = sp1_2 * sp * sp + sp2_2 * cp * cp;
    float Cp = (sp1_2 - sp2_2) * cp * sp;

    float At = st1_2 * ct * ct + st2_2 * st * st;
    float Bt = st1_2 * st * st + st2_2 * ct * ct;
    float Ct = (st1_2 - st2_2) * ct * st;

    float tr_pt = Ap * At + Bp * Bt + 2.0f * Cp * Ct;
    float det_sqrt = sqrtf(fmaxf(s1p * s2p * s1t * s2t, 0.0f));

    float whr = sp1_2 + sp2_2 + st1_2 + st2_2
              - 2.0f * sqrtf(fmaxf(tr_pt + 2.0f * det_sqrt, 0.0f));

    float dist = fmaxf(xy_dist + whr, 0.0f);
    return 1.0f - 1.0f / (1.0f + dist);
}

// One block per batch row (64 KB). TMA bulk double-buffer: the TMA engine
// owns all in-flight bytes (no registers, no LDG issue cost). tid0 issues
// 16 KB chunks; 256 threads scan each chunk from smem branchlessly.
__global__ void __launch_bounds__(THREADS)
gwd_fused_kernel(const float* __restrict__ hm,
                 const float* __restrict__ ab,
                 const float* __restrict__ trig,
                 const float* __restrict__ center,
                 const float* __restrict__ target,
                 float* __restrict__ out,
                 int HW, int B)
{
    const int b = blockIdx.x;
    const int t = threadIdx.x;

    __shared__ alignas(128) float4 buf[2][CHUNK_F4];   // 2 x 16 KB
    __shared__ alignas(8) unsigned long long mbar_store[2];

    const char* row = (const char*)(hm + (size_t)b * HW);
    const int NCHUNK = (HW * 4) / CHUNK_BYTES;         // 4

    const unsigned int m0 = smem_u32(&mbar_store[0]);
    const unsigned int m1 = smem_u32(&mbar_store[1]);
    const unsigned int sbuf0 = smem_u32(&buf[0][0]);
    const unsigned int sbuf1 = smem_u32(&buf[1][0]);

    if (t == 0) {
        mbar_init(m0, 1);
        mbar_init(m1, 1);
        asm volatile("fence.proxy.async.shared::cta;" ::: "memory");
        // Prologue: issue chunks 0 and 1.
        mbar_expect_tx(m0, CHUNK_BYTES);
        bulk_g2s(sbuf0, row, CHUNK_BYTES, m0);
        mbar_expect_tx(m1, CHUNK_BYTES);
        bulk_g2s(sbuf1, row + CHUNK_BYTES, CHUNK_BYTES, m1);
    }
    __syncthreads();

    float best = -CUDART_INF_F;
    int bidx = 0;

    for (int i = 0; i < NCHUNK; i++) {
        const int bi = i & 1;
        mbar_wait(bi ? m1 : m0, (i >> 1) & 1);

        // Consume 4 float4s (conflict-free LDS.128).
        #pragma unroll
        for (int j = 0; j < F4_PER_THREAD; j++) {
            int f4i = t + j * THREADS;
            float4 v = buf[bi][f4i];
            int base = (i * CHUNK_F4 + f4i) << 2;

            float m = fmaxf(fmaxf(v.x, v.y), fmaxf(v.z, v.w));
            int idx4 = (v.z == m) ? (base + 2) : (base + 3);
            idx4     = (v.y == m) ? (base + 1) : idx4;
            idx4     = (v.x == m) ?  base      : idx4;

            bidx = (m > best) ? idx4 : bidx;   // strict > keeps earliest idx
            best = fmaxf(best, m);
        }

        // All threads done reading buf[bi] before refill.
        __syncthreads();
        if (t == 0 && i + 2 < NCHUNK) {
            unsigned int mb = bi ? m1 : m0;
            mbar_expect_tx(mb, CHUNK_BYTES);
            bulk_g2s(bi ? sbuf1 : sbuf0,
                     row + (size_t)(i + 2) * CHUNK_BYTES, CHUNK_BYTES, mb);
        }
    }

    // Pack (sortable value | ~idx): max picks max value, ties -> smallest idx.
    unsigned long long key =
        ((unsigned long long)f2sortable(best) << 32) |
        (unsigned long long)(unsigned int)(~bidx);

    #pragma unroll
    for (int off = 16; off > 0; off >>= 1) {
        unsigned long long o = __shfl_xor_sync(0xffffffffu, key, off);
        key = (o > key) ? o : key;
    }

    __shared__ unsigned long long skey[THREADS / 32];
    if ((t & 31) == 0) skey[t >> 5] = key;
    __syncthreads();
    if (t < 32) {
        unsigned long long k = (t < THREADS / 32) ? skey[t] : 0ull;
        #pragma unroll
        for (int off = 4; off > 0; off >>= 1) {
            unsigned long long o = __shfl_xor_sync(0xffffffffu, k, off);
            k = (o > k) ? o : k;
        }
        if (t == 0) g_keys[b] = k;
    }

    // ---- last-block-done: all epilogues + deterministic mean ----
    __shared__ bool amLast;
    __syncthreads();
    if (t == 0) {
        __threadfence();
        amLast = (atomicAdd(&g_count, 1) == gridDim.x - 1);
    }
    __syncthreads();

    if (amLast) {
        __threadfence();  // make peer g_keys writes visible

        float acc = 0.0f;
        for (int bb = t; bb < B; bb += THREADS) {
            unsigned long long kk = __ldcg(&g_keys[bb]);
            int idx = (int)(~((unsigned int)(kk & 0xffffffffu)));
            acc += gwd_loss_one(ab, trig, center, target, bb, idx, HW);
        }

        __shared__ float sh[THREADS];
        sh[t] = acc;
        __syncthreads();
        #pragma unroll
        for (int s = THREADS / 2; s > 0; s >>= 1) {
            if (t < s) sh[t] += sh[t + s];
            __syncthreads();
        }
        if (t == 0) {
            out[0] = sh[0] / (float)B;
            g_count = 0;  // reset for next graph replay
        }
    }
}

extern "C" void kernel_launch(void* const* d_in, const int* in_sizes, int n_in,
                              void* d_out, int out_size)
{
    const float* hm     = (const float*)d_in[0];  // (B,1,H,W)
    const float* ab     = (const float*)d_in[1];  // (B,2,H,W)
    const float* trig   = (const float*)d_in[2];  // (B,2,H,W)
    const float* center = (const float*)d_in[3];  // (B,2)
    const float* target = (const float*)d_in[4];  // (B,5)
    float* out = (float*)d_out;

    const int B  = in_sizes[4] / 5;
    const int HW = in_sizes[0] / B;   // 16384

    gwd_fused_kernel<<<B, THREADS>>>(hm, ab, trig, center, target, out, HW, B);
}

// round 10
// speedup vs baseline: 1.3585x; 1.3585x over previous
#include <cuda_runtime.h>
#include <math_constants.h>

#define EPS_WH 1e-07f
#define MAX_WH 10000000.0f
#define THREADS 256

// Scratch: per-block argmax keys + completion counter.
__device__ unsigned long long g_keys[4096];
__device__ int g_count;       // zero-initialized; reset by last block each run

__device__ __forceinline__ float clip_wh(float v) {
    return fminf(fmaxf(v, EPS_WH), MAX_WH);
}

__device__ __forceinline__ unsigned int f2sortable(float f) {
    unsigned int u = __float_as_uint(f);
    return (u & 0x80000000u) ? ~u : (u | 0x80000000u);
}

__device__ __forceinline__ float gwd_loss_one(
    const float* __restrict__ ab, const float* __restrict__ trig,
    const float* __restrict__ center, const float* __restrict__ target,
    int b, int idx, int HW)
{
    const float* abb = ab   + (size_t)b * 2 * HW;
    const float* tgb = trig + (size_t)b * 2 * HW;
    float a1    = __ldg(&abb[idx]);
    float a2    = __ldg(&abb[HW + idx]);
    float sin2A = __ldg(&tgb[idx]);
    float cos2A = __ldg(&tgb[HW + idx]);

    // deg roundtrip in the reference is the identity; stay in radians
    float r_p = 0.5f * atan2f(sin2A, cos2A);
    float xp = center[2 * b], yp = center[2 * b + 1];
    float s1p = 0.5f * clip_wh(2.0f * a1);
    float s2p = 0.5f * clip_wh(2.0f * a2);
    float cp = cosf(r_p), sp = sinf(r_p);

    float xt = target[5 * b + 0];
    float yt = target[5 * b + 1];
    float s1t = 0.5f * clip_wh(target[5 * b + 2]);
    float s2t = 0.5f * clip_wh(target[5 * b + 3]);
    float r_t = target[5 * b + 4] * (CUDART_PI_F / 180.0f);
    float ct = cosf(r_t), st = sinf(r_t);

    float dx = xp - xt, dy = yp - yt;
    float xy_dist = dx * dx + dy * dy;

    float sp1_2 = s1p * s1p, sp2_2 = s2p * s2p;
    float st1_2 = s1t * s1t, st2_2 = s2t * s2t;

    float Ap = sp1_2 * cp * cp + sp2_2 * sp * sp;
    float Bp = sp1_2 * sp * sp + sp2_2 * cp * cp;
    float Cp = (sp1_2 - sp2_2) * cp * sp;

    float At = st1_2 * ct * ct + st2_2 * st * st;
    float Bt = st1_2 * st * st + st2_2 * ct * ct;
    float Ct = (st1_2 - st2_2) * ct * st;

    float tr_pt = Ap * At + Bp * Bt + 2.0f * Cp * Ct;
    float det_sqrt = sqrtf(fmaxf(s1p * s2p * s1t * s2t, 0.0f));

    float whr = sp1_2 + sp2_2 + st1_2 + st2_2
              - 2.0f * sqrtf(fmaxf(tr_pt + 2.0f * det_sqrt, 0.0f));

    float dist = fmaxf(xy_dist + whr, 0.0f);
    return 1.0f - 1.0f / (1.0f + dist);
}

// One block per batch row. Hot loop tracks only (best value, best iteration):
// the float4 dies right after folding to its quad-max, keeping register
// pressure low so ptxas can batch loads (register double-buffer guarantees
// >= 2 in flight). The exact element index is recomputed once at the end.
__global__ void __launch_bounds__(THREADS)
gwd_fused_kernel(const float* __restrict__ hm,
                 const float* __restrict__ ab,
                 const float* __restrict__ trig,
                 const float* __restrict__ center,
                 const float* __restrict__ target,
                 float* __restrict__ out,
                 int HW, int B)
{
    const int b = blockIdx.x;
    const int t = threadIdx.x;

    const float4* hm4 = reinterpret_cast<const float4*>(hm + (size_t)b * HW);
    const int NITER = HW >> 10;   // HW / (THREADS*4) = 16

    float best = -CUDART_INF_F;
    int kbest = 0;

    // Register double-buffer: prefetch i+1 before consuming i.
    float4 v = hm4[t];
    #pragma unroll 4
    for (int i = 0; i < NITER; i++) {
        int nx = (i + 1 < NITER) ? (i + 1) : (NITER - 1);   // clamped prefetch
        float4 nv = hm4[nx * THREADS + t];

        float m = fmaxf(fmaxf(v.x, v.y), fmaxf(v.z, v.w));
        kbest = (m > best) ? i : kbest;    // strict > keeps earliest i on ties
        best  = fmaxf(best, m);

        v = nv;
    }

    // Recompute the exact index within the winning quad (one reload, L2-hot).
    {
        float4 vb = hm4[kbest * THREADS + t];
        int base = (kbest * THREADS + t) << 2;
        int idx4 = (vb.z == best) ? (base + 2) : (base + 3);
        idx4     = (vb.y == best) ? (base + 1) : idx4;
        idx4     = (vb.x == best) ?  base      : idx4;
        kbest = idx4;   // now a full element index within the row
    }

    // Pack (sortable value | ~idx): max picks max value, ties -> smallest idx.
    unsigned long long key =
        ((unsigned long long)f2sortable(best) << 32) |
        (unsigned long long)(unsigned int)(~kbest);

    #pragma unroll
    for (int off = 16; off > 0; off >>= 1) {
        unsigned long long o = __shfl_xor_sync(0xffffffffu, key, off);
        key = (o > key) ? o : key;
    }

    __shared__ unsigned long long skey[THREADS / 32];
    if ((t & 31) == 0) skey[t >> 5] = key;
    __syncthreads();
    if (t < 32) {
        unsigned long long k = (t < THREADS / 32) ? skey[t] : 0ull;
        #pragma unroll
        for (int off = 4; off > 0; off >>= 1) {
            unsigned long long o = __shfl_xor_sync(0xffffffffu, k, off);
            k = (o > k) ? o : k;
        }
        if (t == 0) g_keys[b] = k;
    }

    // ---- last-block-done: all epilogues + deterministic mean ----
    __shared__ bool amLast;
    __syncthreads();
    if (t == 0) {
        __threadfence();
        amLast = (atomicAdd(&g_count, 1) == gridDim.x - 1);
    }
    __syncthreads();

    if (amLast) {
        __threadfence();  // make peer g_keys writes visible

        float acc = 0.0f;
        for (int bb = t; bb < B; bb += THREADS) {
            unsigned long long kk = __ldcg(&g_keys[bb]);
            int idx = (int)(~((unsigned int)(kk & 0xffffffffu)));
            acc += gwd_loss_one(ab, trig, center, target, bb, idx, HW);
        }

        __shared__ float sh[THREADS];
        sh[t] = acc;
        __syncthreads();
        #pragma unroll
        for (int s = THREADS / 2; s > 0; s >>= 1) {
            if (t < s) sh[t] += sh[t + s];
            __syncthreads();
        }
        if (t == 0) {
            out[0] = sh[0] / (float)B;
            g_count = 0;  // reset for next graph replay
        }
    }
}

extern "C" void kernel_launch(void* const* d_in, const int* in_sizes, int n_in,
                              void* d_out, int out_size)
{
    const float* hm     = (const float*)d_in[0];  // (B,1,H,W)
    const float* ab     = (const float*)d_in[1];  // (B,2,H,W)
    const float* trig   = (const float*)d_in[2];  // (B,2,H,W)
    const float* center = (const float*)d_in[3];  // (B,2)
    const float* target = (const float*)d_in[4];  // (B,5)
    float* out = (float*)d_out;

    const int B  = in_sizes[4] / 5;
    const int HW = in_sizes[0] / B;   // 16384

    gwd_fused_kernel<<<B, THREADS>>>(hm, ab, trig, center, target, out, HW, B);
}

// round 13
// speedup vs baseline: 1.3636x; 1.0038x over previous
#include <cuda_runtime.h>
#include <math_constants.h>

#define EPS_WH 1e-07f
#define MAX_WH 10000000.0f
#define THREADS 256

// Scratch: per-block argmax keys + completion counter.
__device__ unsigned long long g_keys[4096];
__device__ int g_count;       // zero-initialized; reset by last block each run

__device__ __forceinline__ float clip_wh(float v) {
    return fminf(fmaxf(v, EPS_WH), MAX_WH);
}

__device__ __forceinline__ unsigned int f2sortable(float f) {
    unsigned int u = __float_as_uint(f);
    return (u & 0x80000000u) ? ~u : (u | 0x80000000u);
}

__device__ __forceinline__ float gwd_loss_one(
    const float* __restrict__ ab, const float* __restrict__ trig,
    const float* __restrict__ center, const float* __restrict__ target,
    int b, int idx, int HW)
{
    const float* abb = ab   + (size_t)b * 2 * HW;
    const float* tgb = trig + (size_t)b * 2 * HW;
    float a1    = __ldg(&abb[idx]);
    float a2    = __ldg(&abb[HW + idx]);
    float sin2A = __ldg(&tgb[idx]);
    float cos2A = __ldg(&tgb[HW + idx]);

    // deg roundtrip in the reference is the identity; stay in radians
    float r_p = 0.5f * atan2f(sin2A, cos2A);
    float xp = center[2 * b], yp = center[2 * b + 1];
    float s1p = 0.5f * clip_wh(2.0f * a1);
    float s2p = 0.5f * clip_wh(2.0f * a2);
    float cp = cosf(r_p), sp = sinf(r_p);

    float xt = target[5 * b + 0];
    float yt = target[5 * b + 1];
    float s1t = 0.5f * clip_wh(target[5 * b + 2]);
    float s2t = 0.5f * clip_wh(target[5 * b + 3]);
    float r_t = target[5 * b + 4] * (CUDART_PI_F / 180.0f);
    float ct = cosf(r_t), st = sinf(r_t);

    float dx = xp - xt, dy = yp - yt;
    float xy_dist = dx * dx + dy * dy;

    float sp1_2 = s1p * s1p, sp2_2 = s2p * s2p;
    float st1_2 = s1t * s1t, st2_2 = s2t * s2t;

    float Ap = sp1_2 * cp * cp + sp2_2 * sp * sp;
    float Bp = sp1_2 * sp * sp + sp2_2 * cp * cp;
    float Cp = (sp1_2 - sp2_2) * cp * sp;

    float At = st1_2 * ct * ct + st2_2 * st * st;
    float Bt = st1_2 * st * st + st2_2 * ct * ct;
    float Ct = (st1_2 - st2_2) * ct * st;

    float tr_pt = Ap * At + Bp * Bt + 2.0f * Cp * Ct;
    float det_sqrt = sqrtf(fmaxf(s1p * s2p * s1t * s2t, 0.0f));

    float whr = sp1_2 + sp2_2 + st1_2 + st2_2
              - 2.0f * sqrtf(fmaxf(tr_pt + 2.0f * det_sqrt, 0.0f));

    float dist = fmaxf(xy_dist + whr, 0.0f);
    return 1.0f - 1.0f / (1.0f + dist);
}

// One block per batch row. Two independent (best, bidx) chains consuming two
// back-to-back LDG.128s per iteration: guarantees 2 outstanding loads per
// warp (past the Little's-law knee) with no loop-carried load dependence,
// and halves the serial FMNMX/SEL chain. Last block runs all epilogues.
__global__ void __launch_bounds__(THREADS)
gwd_fused_kernel(const float* __restrict__ hm,
                 const float* __restrict__ ab,
                 const float* __restrict__ trig,
                 const float* __restrict__ center,
                 const float* __restrict__ target,
                 float* __restrict__ out,
                 int HW, int B)
{
    const int b = blockIdx.x;
    const int t = threadIdx.x;

    const float4* hm4 = reinterpret_cast<const float4*>(hm + (size_t)b * HW);
    const int n4 = HW >> 2;               // 4096 float4 per row
    const int STEP = 2 * THREADS;         // two quads per iteration

    float best0 = -CUDART_INF_F, best1 = -CUDART_INF_F;
    int bidx0 = 0, bidx1 = 0;

    #pragma unroll 4
    for (int i = t; i < n4; i += STEP) {
        // Two independent streaming loads, issued back-to-back.
        float4 v0 = __ldcs(&hm4[i]);
        float4 v1 = __ldcs(&hm4[i + THREADS]);

        // Chain 0
        {
            int base = i << 2;
            float m = fmaxf(fmaxf(v0.x, v0.y), fmaxf(v0.z, v0.w));
            int idx4 = (v0.z == m) ? (base + 2) : (base + 3);
            idx4     = (v0.y == m) ? (base + 1) : idx4;
            idx4     = (v0.x == m) ?  base      : idx4;
            bidx0 = (m > best0) ? idx4 : bidx0;
            best0 = fmaxf(best0, m);
        }
        // Chain 1 (independent)
        {
            int base = (i + THREADS) << 2;
            float m = fmaxf(fmaxf(v1.x, v1.y), fmaxf(v1.z, v1.w));
            int idx4 = (v1.z == m) ? (base + 2) : (base + 3);
            idx4     = (v1.y == m) ? (base + 1) : idx4;
            idx4     = (v1.x == m) ?  base      : idx4;
            bidx1 = (m > best1) ? idx4 : bidx1;
            best1 = fmaxf(best1, m);
        }
    }

    // Merge the two chains via packed keys (ties -> smaller index, which
    // preserves exact first-occurrence semantics).
    unsigned long long key0 =
        ((unsigned long long)f2sortable(best0) << 32) |
        (unsigned long long)(unsigned int)(~bidx0);
    unsigned long long key1 =
        ((unsigned long long)f2sortable(best1) << 32) |
        (unsigned long long)(unsigned int)(~bidx1);
    unsigned long long key = (key1 > key0) ? key1 : key0;

    #pragma unroll
    for (int off = 16; off > 0; off >>= 1) {
        unsigned long long o = __shfl_xor_sync(0xffffffffu, key, off);
        key = (o > key) ? o : key;
    }

    __shared__ unsigned long long skey[THREADS / 32];
    if ((t & 31) == 0) skey[t >> 5] = key;
    __syncthreads();
    if (t < 32) {
        unsigned long long k = (t < THREADS / 32) ? skey[t] : 0ull;
        #pragma unroll
        for (int off = 4; off > 0; off >>= 1) {
            unsigned long long o = __shfl_xor_sync(0xffffffffu, k, off);
            k = (o > k) ? o : k;
        }
        if (t == 0) g_keys[b] = k;
    }

    // ---- last-block-done: all epilogues + deterministic mean ----
    __shared__ bool amLast;
    __syncthreads();
    if (t == 0) {
        __threadfence();
        amLast = (atomicAdd(&g_count, 1) == gridDim.x - 1);
    }
    __syncthreads();

    if (amLast) {
        __threadfence();  // make peer g_keys writes visible

        float acc = 0.0f;
        for (int bb = t; bb < B; bb += THREADS) {
            unsigned long long kk = __ldcg(&g_keys[bb]);
            int idx = (int)(~((unsigned int)(kk & 0xffffffffu)));
            acc += gwd_loss_one(ab, trig, center, target, bb, idx, HW);
        }

        __shared__ float sh[THREADS];
        sh[t] = acc;
        __syncthreads();
        #pragma unroll
        for (int s = THREADS / 2; s > 0; s >>= 1) {
            if (t < s) sh[t] += sh[t + s];
            __syncthreads();
        }
        if (t == 0) {
            out[0] = sh[0] / (float)B;
            g_count = 0;  // reset for next graph replay
        }
    }
}

extern "C" void kernel_launch(void* const* d_in, const int* in_sizes, int n_in,
                              void* d_out, int out_size)
{
    const float* hm     = (const float*)d_in[0];  // (B,1,H,W)
    const float* ab     = (const float*)d_in[1];  // (B,2,H,W)
    const float* trig   = (const float*)d_in[2];  // (B,2,H,W)
    const float* center = (const float*)d_in[3];  // (B,2)
    const float* target = (const float*)d_in[4];  // (B,5)
    float* out = (float*)d_out;

    const int B  = in_sizes[4] / 5;
    const int HW = in_sizes[0] / B;   // 16384

    gwd_fused_kernel<<<B, THREADS>>>(hm, ab, trig, center, target, out, HW, B);
}